// round 15
// baseline (speedup 1.0000x reference)
#include <cuda_runtime.h>
#include <cuda_bf16.h>
#include <mma.h>
#include <math.h>

using namespace nvcuda;

#define TPB 512
#define SMEM_BYTES 106496  // max(DO=128: 69632+34816, DO=64: 36864+69632)

// Scratch (__device__ globals; statically zero-initialized).
// ZERO-INVARIANT: g_cnt, g_fill, g_cursor, g_barc, g_bars are zero at entry of
// every call; the kernel's last phase + epilogue restore this.
__device__ float g_xw[100000 * 128];
__device__ float g_h[100000 * 128];
__device__ float g_dinv[100000];
__device__ int   g_cnt[100000];
__device__ int   g_fill[100000];
__device__ int   g_ptr[100000];
__device__ int   g_cursor;
__device__ int2  g_edge[1600000];
__device__ unsigned g_barc;   // monotonic arrival counter
__device__ unsigned g_bars;   // release phase flag

// Device-wide barrier (all nb blocks co-resident). Monotonic phases 1,2,3,...
__device__ __forceinline__ void gsync(unsigned phase, int nb) {
    __syncthreads();
    if (threadIdx.x == 0) {
        __threadfence();
        atomicAdd(&g_barc, 1u);
        if (blockIdx.x == 0) {
            while (atomicAdd(&g_barc, 0u) < (unsigned)nb * phase) __nanosleep(64);
            atomicExch(&g_bars, phase);
        } else {
            while (atomicAdd(&g_bars, 0u) < phase) __nanosleep(64);
        }
        __threadfence();
    }
    __syncthreads();
}

// ---------------------------------------------------------------------------
// Aggregation phase: warp per node (grid-stride), lane owns float4 (128 f).
// out[v] = dinv[v]^2*in[v] + sum_e norm[e]*in[src[e]]
// (identical inner loop to the 473us round-14 version: MLP=4, scalar tail)
// ---------------------------------------------------------------------------
__device__ void aggr128(const float* __restrict__ in, float* __restrict__ out,
                        int N, int gwarp, int nwarps) {
    const int lane = threadIdx.x & 31;
    for (int w = gwarp; w < N; w += nwarps) {
        const int beg = g_ptr[w];
        const int end = beg + g_cnt[w];
        const float dv = g_dinv[w];
        const float s = dv * dv;

        float4 acc = *(const float4*)&in[(size_t)w * 128 + lane * 4];
        acc.x *= s; acc.y *= s; acc.z *= s; acc.w *= s;

        for (int base = beg; base < end; base += 32) {
            const int idx = base + lane;
            const int2 ed = (idx < end) ? g_edge[idx] : make_int2(0, 0);
            const int m = min(32, end - base);
            int j = 0;
            for (; j + 4 <= m; j += 4) {
                const int s0 = __shfl_sync(0xffffffffu, ed.x, j + 0);
                const int s1 = __shfl_sync(0xffffffffu, ed.x, j + 1);
                const int s2 = __shfl_sync(0xffffffffu, ed.x, j + 2);
                const int s3 = __shfl_sync(0xffffffffu, ed.x, j + 3);
                const float n0 = __int_as_float(__shfl_sync(0xffffffffu, ed.y, j + 0));
                const float n1 = __int_as_float(__shfl_sync(0xffffffffu, ed.y, j + 1));
                const float n2 = __int_as_float(__shfl_sync(0xffffffffu, ed.y, j + 2));
                const float n3 = __int_as_float(__shfl_sync(0xffffffffu, ed.y, j + 3));
                const float4 v0 = *(const float4*)&in[(size_t)s0 * 128 + lane * 4];
                const float4 v1 = *(const float4*)&in[(size_t)s1 * 128 + lane * 4];
                const float4 v2 = *(const float4*)&in[(size_t)s2 * 128 + lane * 4];
                const float4 v3 = *(const float4*)&in[(size_t)s3 * 128 + lane * 4];
                acc.x = fmaf(n0, v0.x, acc.x); acc.y = fmaf(n0, v0.y, acc.y);
                acc.z = fmaf(n0, v0.z, acc.z); acc.w = fmaf(n0, v0.w, acc.w);
                acc.x = fmaf(n1, v1.x, acc.x); acc.y = fmaf(n1, v1.y, acc.y);
                acc.z = fmaf(n1, v1.z, acc.z); acc.w = fmaf(n1, v1.w, acc.w);
                acc.x = fmaf(n2, v2.x, acc.x); acc.y = fmaf(n2, v2.y, acc.y);
                acc.z = fmaf(n2, v2.z, acc.z); acc.w = fmaf(n2, v2.w, acc.w);
                acc.x = fmaf(n3, v3.x, acc.x); acc.y = fmaf(n3, v3.y, acc.y);
                acc.z = fmaf(n3, v3.z, acc.z); acc.w = fmaf(n3, v3.w, acc.w);
            }
            for (; j < m; j++) {
                const int s0 = __shfl_sync(0xffffffffu, ed.x, j);
                const float n0 = __int_as_float(__shfl_sync(0xffffffffu, ed.y, j));
                const float4 v0 = *(const float4*)&in[(size_t)s0 * 128 + lane * 4];
                acc.x = fmaf(n0, v0.x, acc.x); acc.y = fmaf(n0, v0.y, acc.y);
                acc.z = fmaf(n0, v0.z, acc.z); acc.w = fmaf(n0, v0.w, acc.w);
            }
        }

        *(float4*)&out[(size_t)w * 128 + lane * 4] = acc;
    }
}

// ---------------------------------------------------------------------------
// Tensor-core GEMM phase (bf16 3-term split, fp32 accumulate):
// B[N,DO] = (A[N,128] @ W[128,DO]) + bias, optional ReLU.
// 16 warps; tile M nodes x DO cols; each warp: 1 m-tile x 2 n-tiles.
// DO=128: M=64 (4 m-tiles x 8 n-tiles); DO=64: M=128 (8 x 4).
// ---------------------------------------------------------------------------
template <int DO, int M, bool RELU>
__device__ void gemm_tc(const float* __restrict__ A, const float* __restrict__ W,
                        const float* __restrict__ bias, float* __restrict__ B,
                        int N, char* smem, int nb) {
    constexpr int LDW = DO + 8;        // padded W row
    constexpr int LDA = 136;           // padded A row (128 + 8)
    constexpr int NT = DO / 16;        // n-tiles
    constexpr int TPW = 2;             // n-tiles per warp
    constexpr int WPR = NT / TPW;      // warps per m-tile row
    static_assert((M / 16) * WPR == TPB / 32, "all warps used");
    __nv_bfloat16* w_hi = (__nv_bfloat16*)smem;
    __nv_bfloat16* w_lo = w_hi + 128 * LDW;
    __nv_bfloat16* a_hi = w_lo + 128 * LDW;
    __nv_bfloat16* a_lo = a_hi + M * LDA;
    float* outs = (float*)(w_lo + 128 * LDW);  // aliases a_hi/a_lo after MMA

    const int tid = threadIdx.x;
    const int warp = tid >> 5;
    const int wm = warp / WPR;           // m-tile
    const int wn0 = (warp % WPR) * TPW;  // first n-tile

    // stage W -> bf16 hi/lo (once per phase)
    for (int i = tid; i < 128 * DO / 4; i += TPB) {
        const int r = i / (DO / 4);
        const int c4 = i % (DO / 4);
        const float4 v = *(const float4*)&W[r * DO + c4 * 4];
        __nv_bfloat16 h0 = __float2bfloat16(v.x), h1 = __float2bfloat16(v.y);
        __nv_bfloat16 h2 = __float2bfloat16(v.z), h3 = __float2bfloat16(v.w);
        __nv_bfloat16* ph = &w_hi[r * LDW + c4 * 4];
        __nv_bfloat16* pl = &w_lo[r * LDW + c4 * 4];
        ph[0] = h0; ph[1] = h1; ph[2] = h2; ph[3] = h3;
        pl[0] = __float2bfloat16(v.x - __bfloat162float(h0));
        pl[1] = __float2bfloat16(v.y - __bfloat162float(h1));
        pl[2] = __float2bfloat16(v.z - __bfloat162float(h2));
        pl[3] = __float2bfloat16(v.w - __bfloat162float(h3));
    }

    const int n_tiles = (N + M - 1) / M;
    for (int tile = blockIdx.x; tile < n_tiles; tile += nb) {
        const int base = tile * M;
        __syncthreads();  // W staged / outs (a-region) free from previous tile
        // stage A tile -> bf16 hi/lo
        for (int i = tid; i < M * 32; i += TPB) {
            const int r = i >> 5;
            const int c4 = i & 31;
            const int node = base + r;
            float4 v = make_float4(0.f, 0.f, 0.f, 0.f);
            if (node < N) v = *(const float4*)&A[(size_t)node * 128 + c4 * 4];
            __nv_bfloat16 h0 = __float2bfloat16(v.x), h1 = __float2bfloat16(v.y);
            __nv_bfloat16 h2 = __float2bfloat16(v.z), h3 = __float2bfloat16(v.w);
            __nv_bfloat16* ph = &a_hi[r * LDA + c4 * 4];
            __nv_bfloat16* pl = &a_lo[r * LDA + c4 * 4];
            ph[0] = h0; ph[1] = h1; ph[2] = h2; ph[3] = h3;
            pl[0] = __float2bfloat16(v.x - __bfloat162float(h0));
            pl[1] = __float2bfloat16(v.y - __bfloat162float(h1));
            pl[2] = __float2bfloat16(v.z - __bfloat162float(h2));
            pl[3] = __float2bfloat16(v.w - __bfloat162float(h3));
        }
        __syncthreads();

        wmma::fragment<wmma::accumulator, 16, 16, 16, float> acc[TPW];
#pragma unroll
        for (int t = 0; t < TPW; t++) wmma::fill_fragment(acc[t], 0.0f);

#pragma unroll
        for (int k = 0; k < 128; k += 16) {
            wmma::fragment<wmma::matrix_a, 16, 16, 16, __nv_bfloat16, wmma::row_major> fah, fal;
            wmma::load_matrix_sync(fah, a_hi + wm * 16 * LDA + k, LDA);
            wmma::load_matrix_sync(fal, a_lo + wm * 16 * LDA + k, LDA);
#pragma unroll
            for (int t = 0; t < TPW; t++) {
                const int nt = wn0 + t;
                wmma::fragment<wmma::matrix_b, 16, 16, 16, __nv_bfloat16, wmma::row_major> fbh, fbl;
                wmma::load_matrix_sync(fbh, w_hi + k * LDW + nt * 16, LDW);
                wmma::load_matrix_sync(fbl, w_lo + k * LDW + nt * 16, LDW);
                wmma::mma_sync(acc[t], fah, fbh, acc[t]);
                wmma::mma_sync(acc[t], fah, fbl, acc[t]);
                wmma::mma_sync(acc[t], fal, fbh, acc[t]);
            }
        }

        __syncthreads();  // all warps done reading a_hi/a_lo (outs aliases them)
#pragma unroll
        for (int t = 0; t < TPW; t++)
            wmma::store_matrix_sync(outs + wm * 16 * DO + (wn0 + t) * 16, acc[t],
                                    DO, wmma::mem_row_major);
        __syncthreads();

        // epilogue: bias + optional relu, write to global
        for (int i = tid; i < M * DO / 4; i += TPB) {
            const int r = i / (DO / 4);
            const int c4 = i % (DO / 4);
            const int node = base + r;
            if (node < N) {
                float4 v = *(const float4*)&outs[r * DO + c4 * 4];
                const float4 bb = *(const float4*)&bias[c4 * 4];
                v.x += bb.x; v.y += bb.y; v.z += bb.z; v.w += bb.w;
                if (RELU) {
                    v.x = fmaxf(v.x, 0.f); v.y = fmaxf(v.y, 0.f);
                    v.z = fmaxf(v.z, 0.f); v.w = fmaxf(v.w, 0.f);
                }
                *(float4*)&B[(size_t)node * DO + c4 * 4] = v;
            }
        }
    }
}

// ---------------------------------------------------------------------------
// The fused persistent kernel: whole 3-layer GCN in one launch.
// __launch_bounds__(512, 2): 32 warps/SM resident (vs 24 at TPB=384).
// ---------------------------------------------------------------------------
__global__ void __launch_bounds__(TPB, 2)
k_fused(const float* __restrict__ x,
        const int* __restrict__ row, const int* __restrict__ col,
        const float* __restrict__ W1, const float* __restrict__ b1,
        const float* __restrict__ W2, const float* __restrict__ b2,
        const float* __restrict__ W3, const float* __restrict__ b3,
        float* __restrict__ out, int N, int E, int nb) {
    extern __shared__ char sh[];
    const int gtid = blockIdx.x * TPB + threadIdx.x;
    const int gthreads = nb * TPB;
    const int gwarp = gtid >> 5;
    const int nwarps = gthreads >> 5;
    const int lane = threadIdx.x & 31;

    // P0: degree histogram (g_cnt zero by invariant)
    for (int e = gtid; e < E; e += gthreads) atomicAdd(&g_cnt[col[e]], 1);
    gsync(1, nb);

    // P1: segment alloc (warp scan + global cursor) + dinv
    for (int cb = gwarp; cb * 32 < N; cb += nwarps) {
        const int i = cb * 32 + lane;
        const int c = (i < N) ? g_cnt[i] : 0;
        int p = c;
#pragma unroll
        for (int off = 1; off < 32; off <<= 1) {
            const int t = __shfl_up_sync(0xffffffffu, p, off);
            if (lane >= off) p += t;
        }
        const int total = __shfl_sync(0xffffffffu, p, 31);
        int base = 0;
        if (lane == 31) base = atomicAdd(&g_cursor, total);
        base = __shfl_sync(0xffffffffu, base, 31);
        if (i < N) {
            g_ptr[i] = base + p - c;
            g_dinv[i] = rsqrtf((float)(c + 1));  // +1 self-loop
        }
    }
    gsync(2, nb);

    // P2: fill edges {src, norm}
    for (int e = gtid; e < E; e += gthreads) {
        const int c = col[e];
        const int r = row[e];
        const int pos = g_ptr[c] + atomicAdd(&g_fill[c], 1);
        g_edge[pos] = make_int2(r, __float_as_int(g_dinv[r] * g_dinv[c]));
    }
    gsync(3, nb);

    // layer 1
    aggr128(x, g_h, N, gwarp, nwarps);
    gsync(4, nb);
    gemm_tc<128, 64, true>(g_h, W1, b1, g_xw, N, sh, nb);
    gsync(5, nb);

    // layer 2
    aggr128(g_xw, g_h, N, gwarp, nwarps);
    gsync(6, nb);
    gemm_tc<128, 64, true>(g_h, W2, b2, g_xw, N, sh, nb);
    gsync(7, nb);

    // layer 3
    aggr128(g_xw, g_h, N, gwarp, nwarps);
    gsync(8, nb);

    // cleanup (restore zero-invariant) — independent of gemm3's data
    for (int i = gtid; i < N; i += gthreads) { g_cnt[i] = 0; g_fill[i] = 0; }
    if (gtid == 0) g_cursor = 0;

    gemm_tc<64, 128, false>(g_h, W3, b3, out, N, sh, nb);

    // epilogue: reset barrier state after all blocks passed gsync(8)+finished.
    __syncthreads();
    if (threadIdx.x == 0) {
        __threadfence();
        if (blockIdx.x != 0) {
            atomicAdd(&g_barc, 1u);
        } else {
            while (atomicAdd(&g_barc, 0u) < (unsigned)nb * 8u + (unsigned)(nb - 1))
                __nanosleep(64);
            atomicExch(&g_barc, 0u);
            atomicExch(&g_bars, 0u);
        }
    }
}

// ---------------------------------------------------------------------------
// launch — ONE kernel
// ---------------------------------------------------------------------------
extern "C" void kernel_launch(void* const* d_in, const int* in_sizes, int n_in,
                              void* d_out, int out_size) {
    const float* x  = (const float*)d_in[0];
    const int*   ei = (const int*)d_in[1];
    const float* W1 = (const float*)d_in[2];
    const float* b1 = (const float*)d_in[3];
    const float* W2 = (const float*)d_in[4];
    const float* b2 = (const float*)d_in[5];
    const float* W3 = (const float*)d_in[6];
    const float* b3 = (const float*)d_in[7];
    float* out = (float*)d_out;

    const int N = in_sizes[0] / 128;
    const int E = in_sizes[1] / 2;
    const int* row = ei;
    const int* col = ei + E;

    cudaFuncSetAttribute(k_fused, cudaFuncAttributeMaxDynamicSharedMemorySize, SMEM_BYTES);

    int dev = 0;
    cudaGetDevice(&dev);
    int sms = 0;
    cudaDeviceGetAttribute(&sms, cudaDevAttrMultiProcessorCount, dev);
    int bpm = 0;
    cudaOccupancyMaxActiveBlocksPerMultiprocessor(&bpm, k_fused, TPB, SMEM_BYTES);
    if (bpm < 1) bpm = 1;
    if (bpm > 2) bpm = 2;
    const int nb = sms * bpm;   // all blocks co-resident -> gsync is safe

    k_fused<<<nb, TPB, SMEM_BYTES>>>(x, row, col, W1, b1, W2, b2, W3, b3, out, N, E, nb);
}

// round 16
// speedup vs baseline: 1.0665x; 1.0665x over previous
#include <cuda_runtime.h>
#include <cuda_bf16.h>
#include <mma.h>
#include <math.h>

using namespace nvcuda;

#define TPB 384
#define SMEM_BYTES 95744   // max(DO=128: 69632+26112, DO=64: 36864+52224)

// Scratch (__device__ globals; statically zero-initialized).
// ZERO-INVARIANT: g_cnt, g_fill, g_cursor, g_barc, g_bars are zero at entry of
// every call; the kernel's last phase + epilogue restore this.
__device__ float g_xw[100000 * 128];
__device__ float g_h[100000 * 128];
__device__ float g_dinv[100000];
__device__ int   g_cnt[100000];
__device__ int   g_fill[100000];
__device__ int   g_ptr[100000];
__device__ int   g_cursor;
__device__ int2  g_edge[1600000];
__device__ unsigned g_barc;   // monotonic arrival counter
__device__ unsigned g_bars;   // release phase flag

// Device-wide barrier (all nb blocks co-resident). Monotonic phases 1,2,3,...
__device__ __forceinline__ void gsync(unsigned phase, int nb) {
    __syncthreads();
    if (threadIdx.x == 0) {
        __threadfence();
        atomicAdd(&g_barc, 1u);
        if (blockIdx.x == 0) {
            while (atomicAdd(&g_barc, 0u) < (unsigned)nb * phase) __nanosleep(64);
            atomicExch(&g_bars, phase);
        } else {
            while (atomicAdd(&g_bars, 0u) < phase) __nanosleep(64);
        }
        __threadfence();
    }
    __syncthreads();
}

// ---------------------------------------------------------------------------
// Aggregation phase: warp per node (grid-stride), lane owns float4 (128 f).
// out[v] = dinv[v]^2*in[v] + sum_e norm[e]*in[src[e]]
// MLP=8: eight gathers issued back-to-back before any accumulation.
// ---------------------------------------------------------------------------
__device__ void aggr128(const float* __restrict__ in, float* __restrict__ out,
                        int N, int gwarp, int nwarps) {
    const int lane = threadIdx.x & 31;
    for (int w = gwarp; w < N; w += nwarps) {
        const int beg = g_ptr[w];
        const int end = beg + g_cnt[w];
        const float dv = g_dinv[w];
        const float s = dv * dv;

        float4 acc = *(const float4*)&in[(size_t)w * 128 + lane * 4];
        acc.x *= s; acc.y *= s; acc.z *= s; acc.w *= s;

        for (int base = beg; base < end; base += 32) {
            const int idx = base + lane;
            const int2 ed = (idx < end) ? g_edge[idx] : make_int2(0, 0);
            const int m = min(32, end - base);
            int j = 0;
            for (; j + 8 <= m; j += 8) {
                int sx[8];
                float nm[8];
#pragma unroll
                for (int q = 0; q < 8; q++) {
                    sx[q] = __shfl_sync(0xffffffffu, ed.x, j + q);
                    nm[q] = __int_as_float(__shfl_sync(0xffffffffu, ed.y, j + q));
                }
                float4 v[8];
#pragma unroll
                for (int q = 0; q < 8; q++)
                    v[q] = *(const float4*)&in[(size_t)sx[q] * 128 + lane * 4];
#pragma unroll
                for (int q = 0; q < 8; q++) {
                    acc.x = fmaf(nm[q], v[q].x, acc.x);
                    acc.y = fmaf(nm[q], v[q].y, acc.y);
                    acc.z = fmaf(nm[q], v[q].z, acc.z);
                    acc.w = fmaf(nm[q], v[q].w, acc.w);
                }
            }
            for (; j + 4 <= m; j += 4) {
                const int s0 = __shfl_sync(0xffffffffu, ed.x, j + 0);
                const int s1 = __shfl_sync(0xffffffffu, ed.x, j + 1);
                const int s2 = __shfl_sync(0xffffffffu, ed.x, j + 2);
                const int s3 = __shfl_sync(0xffffffffu, ed.x, j + 3);
                const float n0 = __int_as_float(__shfl_sync(0xffffffffu, ed.y, j + 0));
                const float n1 = __int_as_float(__shfl_sync(0xffffffffu, ed.y, j + 1));
                const float n2 = __int_as_float(__shfl_sync(0xffffffffu, ed.y, j + 2));
                const float n3 = __int_as_float(__shfl_sync(0xffffffffu, ed.y, j + 3));
                const float4 v0 = *(const float4*)&in[(size_t)s0 * 128 + lane * 4];
                const float4 v1 = *(const float4*)&in[(size_t)s1 * 128 + lane * 4];
                const float4 v2 = *(const float4*)&in[(size_t)s2 * 128 + lane * 4];
                const float4 v3 = *(const float4*)&in[(size_t)s3 * 128 + lane * 4];
                acc.x = fmaf(n0, v0.x, acc.x); acc.y = fmaf(n0, v0.y, acc.y);
                acc.z = fmaf(n0, v0.z, acc.z); acc.w = fmaf(n0, v0.w, acc.w);
                acc.x = fmaf(n1, v1.x, acc.x); acc.y = fmaf(n1, v1.y, acc.y);
                acc.z = fmaf(n1, v1.z, acc.z); acc.w = fmaf(n1, v1.w, acc.w);
                acc.x = fmaf(n2, v2.x, acc.x); acc.y = fmaf(n2, v2.y, acc.y);
                acc.z = fmaf(n2, v2.z, acc.z); acc.w = fmaf(n2, v2.w, acc.w);
                acc.x = fmaf(n3, v3.x, acc.x); acc.y = fmaf(n3, v3.y, acc.y);
                acc.z = fmaf(n3, v3.z, acc.z); acc.w = fmaf(n3, v3.w, acc.w);
            }
            for (; j < m; j++) {
                const int s0 = __shfl_sync(0xffffffffu, ed.x, j);
                const float n0 = __int_as_float(__shfl_sync(0xffffffffu, ed.y, j));
                const float4 v0 = *(const float4*)&in[(size_t)s0 * 128 + lane * 4];
                acc.x = fmaf(n0, v0.x, acc.x); acc.y = fmaf(n0, v0.y, acc.y);
                acc.z = fmaf(n0, v0.z, acc.z); acc.w = fmaf(n0, v0.w, acc.w);
            }
        }

        *(float4*)&out[(size_t)w * 128 + lane * 4] = acc;
    }
}

// ---------------------------------------------------------------------------
// Tensor-core GEMM phase (bf16 3-term split, fp32 accumulate):
// B[N,DO] = (A[N,128] @ W[128,DO]) + bias, optional ReLU.
// 12 warps; tile M nodes x DO cols; each warp: 1 m-tile x 2 n-tiles.
// DO=128: M=48 (3 m-tiles x 8 n-tiles); DO=64: M=96 (6 x 4).
// ---------------------------------------------------------------------------
template <int DO, int M, bool RELU>
__device__ void gemm_tc(const float* __restrict__ A, const float* __restrict__ W,
                        const float* __restrict__ bias, float* __restrict__ B,
                        int N, char* smem, int nb) {
    constexpr int LDW = DO + 8;        // padded W row
    constexpr int LDA = 136;           // padded A row (128 + 8)
    constexpr int NT = DO / 16;        // n-tiles
    constexpr int TPW = 2;             // n-tiles per warp
    constexpr int WPR = NT / TPW;      // warps per m-tile row
    static_assert((M / 16) * WPR == 12, "12 warps");
    __nv_bfloat16* w_hi = (__nv_bfloat16*)smem;
    __nv_bfloat16* w_lo = w_hi + 128 * LDW;
    __nv_bfloat16* a_hi = w_lo + 128 * LDW;
    __nv_bfloat16* a_lo = a_hi + M * LDA;
    float* outs = (float*)(w_lo + 128 * LDW);  // aliases a_hi/a_lo after MMA

    const int tid = threadIdx.x;
    const int warp = tid >> 5;
    const int wm = warp / WPR;           // m-tile
    const int wn0 = (warp % WPR) * TPW;  // first n-tile

    // stage W -> bf16 hi/lo (once per phase)
    for (int i = tid; i < 128 * DO / 4; i += TPB) {
        const int r = i / (DO / 4);
        const int c4 = i % (DO / 4);
        const float4 v = *(const float4*)&W[r * DO + c4 * 4];
        __nv_bfloat16 h0 = __float2bfloat16(v.x), h1 = __float2bfloat16(v.y);
        __nv_bfloat16 h2 = __float2bfloat16(v.z), h3 = __float2bfloat16(v.w);
        __nv_bfloat16* ph = &w_hi[r * LDW + c4 * 4];
        __nv_bfloat16* pl = &w_lo[r * LDW + c4 * 4];
        ph[0] = h0; ph[1] = h1; ph[2] = h2; ph[3] = h3;
        pl[0] = __float2bfloat16(v.x - __bfloat162float(h0));
        pl[1] = __float2bfloat16(v.y - __bfloat162float(h1));
        pl[2] = __float2bfloat16(v.z - __bfloat162float(h2));
        pl[3] = __float2bfloat16(v.w - __bfloat162float(h3));
    }

    const int n_tiles = (N + M - 1) / M;
    for (int tile = blockIdx.x; tile < n_tiles; tile += nb) {
        const int base = tile * M;
        __syncthreads();  // W staged / outs (a-region) free from previous tile
        // stage A tile -> bf16 hi/lo
        for (int i = tid; i < M * 32; i += TPB) {
            const int r = i >> 5;
            const int c4 = i & 31;
            const int node = base + r;
            float4 v = make_float4(0.f, 0.f, 0.f, 0.f);
            if (node < N) v = *(const float4*)&A[(size_t)node * 128 + c4 * 4];
            __nv_bfloat16 h0 = __float2bfloat16(v.x), h1 = __float2bfloat16(v.y);
            __nv_bfloat16 h2 = __float2bfloat16(v.z), h3 = __float2bfloat16(v.w);
            __nv_bfloat16* ph = &a_hi[r * LDA + c4 * 4];
            __nv_bfloat16* pl = &a_lo[r * LDA + c4 * 4];
            ph[0] = h0; ph[1] = h1; ph[2] = h2; ph[3] = h3;
            pl[0] = __float2bfloat16(v.x - __bfloat162float(h0));
            pl[1] = __float2bfloat16(v.y - __bfloat162float(h1));
            pl[2] = __float2bfloat16(v.z - __bfloat162float(h2));
            pl[3] = __float2bfloat16(v.w - __bfloat162float(h3));
        }
        __syncthreads();

        wmma::fragment<wmma::accumulator, 16, 16, 16, float> acc[TPW];
#pragma unroll
        for (int t = 0; t < TPW; t++) wmma::fill_fragment(acc[t], 0.0f);

#pragma unroll
        for (int k = 0; k < 128; k += 16) {
            wmma::fragment<wmma::matrix_a, 16, 16, 16, __nv_bfloat16, wmma::row_major> fah, fal;
            wmma::load_matrix_sync(fah, a_hi + wm * 16 * LDA + k, LDA);
            wmma::load_matrix_sync(fal, a_lo + wm * 16 * LDA + k, LDA);
#pragma unroll
            for (int t = 0; t < TPW; t++) {
                const int nt = wn0 + t;
                wmma::fragment<wmma::matrix_b, 16, 16, 16, __nv_bfloat16, wmma::row_major> fbh, fbl;
                wmma::load_matrix_sync(fbh, w_hi + k * LDW + nt * 16, LDW);
                wmma::load_matrix_sync(fbl, w_lo + k * LDW + nt * 16, LDW);
                wmma::mma_sync(acc[t], fah, fbh, acc[t]);
                wmma::mma_sync(acc[t], fah, fbl, acc[t]);
                wmma::mma_sync(acc[t], fal, fbh, acc[t]);
            }
        }

        __syncthreads();  // all warps done reading a_hi/a_lo (outs aliases them)
#pragma unroll
        for (int t = 0; t < TPW; t++)
            wmma::store_matrix_sync(outs + wm * 16 * DO + (wn0 + t) * 16, acc[t],
                                    DO, wmma::mem_row_major);
        __syncthreads();

        // epilogue: bias + optional relu, write to global
        for (int i = tid; i < M * DO / 4; i += TPB) {
            const int r = i / (DO / 4);
            const int c4 = i % (DO / 4);
            const int node = base + r;
            if (node < N) {
                float4 v = *(const float4*)&outs[r * DO + c4 * 4];
                const float4 bb = *(const float4*)&bias[c4 * 4];
                v.x += bb.x; v.y += bb.y; v.z += bb.z; v.w += bb.w;
                if (RELU) {
                    v.x = fmaxf(v.x, 0.f); v.y = fmaxf(v.y, 0.f);
                    v.z = fmaxf(v.z, 0.f); v.w = fmaxf(v.w, 0.f);
                }
                *(float4*)&B[(size_t)node * DO + c4 * 4] = v;
            }
        }
    }
}

// ---------------------------------------------------------------------------
// The fused persistent kernel: whole 3-layer GCN in one launch.
// __launch_bounds__(384, 2): 24 warps/SM resident, ~85-reg budget.
// ---------------------------------------------------------------------------
__global__ void __launch_bounds__(TPB, 2)
k_fused(const float* __restrict__ x,
        const int* __restrict__ row, const int* __restrict__ col,
        const float* __restrict__ W1, const float* __restrict__ b1,
        const float* __restrict__ W2, const float* __restrict__ b2,
        const float* __restrict__ W3, const float* __restrict__ b3,
        float* __restrict__ out, int N, int E, int nb) {
    extern __shared__ char sh[];
    const int gtid = blockIdx.x * TPB + threadIdx.x;
    const int gthreads = nb * TPB;
    const int gwarp = gtid >> 5;
    const int nwarps = gthreads >> 5;
    const int lane = threadIdx.x & 31;

    // P0: degree histogram (g_cnt zero by invariant)
    for (int e = gtid; e < E; e += gthreads) atomicAdd(&g_cnt[col[e]], 1);
    gsync(1, nb);

    // P1: segment alloc (warp scan + global cursor) + dinv
    for (int cb = gwarp; cb * 32 < N; cb += nwarps) {
        const int i = cb * 32 + lane;
        const int c = (i < N) ? g_cnt[i] : 0;
        int p = c;
#pragma unroll
        for (int off = 1; off < 32; off <<= 1) {
            const int t = __shfl_up_sync(0xffffffffu, p, off);
            if (lane >= off) p += t;
        }
        const int total = __shfl_sync(0xffffffffu, p, 31);
        int base = 0;
        if (lane == 31) base = atomicAdd(&g_cursor, total);
        base = __shfl_sync(0xffffffffu, base, 31);
        if (i < N) {
            g_ptr[i] = base + p - c;
            g_dinv[i] = rsqrtf((float)(c + 1));  // +1 self-loop
        }
    }
    gsync(2, nb);

    // P2: fill edges {src, norm}
    for (int e = gtid; e < E; e += gthreads) {
        const int c = col[e];
        const int r = row[e];
        const int pos = g_ptr[c] + atomicAdd(&g_fill[c], 1);
        g_edge[pos] = make_int2(r, __float_as_int(g_dinv[r] * g_dinv[c]));
    }
    gsync(3, nb);

    // layer 1
    aggr128(x, g_h, N, gwarp, nwarps);
    gsync(4, nb);
    gemm_tc<128, 48, true>(g_h, W1, b1, g_xw, N, sh, nb);
    gsync(5, nb);

    // layer 2
    aggr128(g_xw, g_h, N, gwarp, nwarps);
    gsync(6, nb);
    gemm_tc<128, 48, true>(g_h, W2, b2, g_xw, N, sh, nb);
    gsync(7, nb);

    // layer 3
    aggr128(g_xw, g_h, N, gwarp, nwarps);
    gsync(8, nb);

    // cleanup (restore zero-invariant) — independent of gemm3's data
    for (int i = gtid; i < N; i += gthreads) { g_cnt[i] = 0; g_fill[i] = 0; }
    if (gtid == 0) g_cursor = 0;

    gemm_tc<64, 96, false>(g_h, W3, b3, out, N, sh, nb);

    // epilogue: reset barrier state after all blocks passed gsync(8)+finished.
    __syncthreads();
    if (threadIdx.x == 0) {
        __threadfence();
        if (blockIdx.x != 0) {
            atomicAdd(&g_barc, 1u);
        } else {
            while (atomicAdd(&g_barc, 0u) < (unsigned)nb * 8u + (unsigned)(nb - 1))
                __nanosleep(64);
            atomicExch(&g_barc, 0u);
            atomicExch(&g_bars, 0u);
        }
    }
}

// ---------------------------------------------------------------------------
// launch — ONE kernel
// ---------------------------------------------------------------------------
extern "C" void kernel_launch(void* const* d_in, const int* in_sizes, int n_in,
                              void* d_out, int out_size) {
    const float* x  = (const float*)d_in[0];
    const int*   ei = (const int*)d_in[1];
    const float* W1 = (const float*)d_in[2];
    const float* b1 = (const float*)d_in[3];
    const float* W2 = (const float*)d_in[4];
    const float* b2 = (const float*)d_in[5];
    const float* W3 = (const float*)d_in[6];
    const float* b3 = (const float*)d_in[7];
    float* out = (float*)d_out;

    const int N = in_sizes[0] / 128;
    const int E = in_sizes[1] / 2;
    const int* row = ei;
    const int* col = ei + E;

    cudaFuncSetAttribute(k_fused, cudaFuncAttributeMaxDynamicSharedMemorySize, SMEM_BYTES);

    int dev = 0;
    cudaGetDevice(&dev);
    int sms = 0;
    cudaDeviceGetAttribute(&sms, cudaDevAttrMultiProcessorCount, dev);
    int bpm = 0;
    cudaOccupancyMaxActiveBlocksPerMultiprocessor(&bpm, k_fused, TPB, SMEM_BYTES);
    if (bpm < 1) bpm = 1;
    if (bpm > 2) bpm = 2;
    const int nb = sms * bpm;   // all blocks co-resident -> gsync is safe

    k_fused<<<nb, TPB, SMEM_BYTES>>>(x, row, col, W1, b1, W2, b2, W3, b3, out, N, E, nb);
}

// round 17
// speedup vs baseline: 1.0978x; 1.0293x over previous
#include <cuda_runtime.h>
#include <cuda_bf16.h>
#include <mma.h>
#include <math.h>

using namespace nvcuda;

#define TPB 384
#define WARPS 12
#define SMEM_BYTES 95744   // max(DO=128: 69632+26112, DO=64: 36864+52224)

// Scratch (__device__ globals; statically zero-initialized).
// ZERO-INVARIANT: g_cnt, g_fill, g_cursor, g_barc, g_bars are zero at entry of
// every call; the kernel's last phase + epilogue restore this.
__device__ float g_xw[100000 * 128];
__device__ float g_dinv[100000];
__device__ int   g_cnt[100000];
__device__ int   g_fill[100000];
__device__ int   g_ptr[100000];
__device__ int   g_cursor;
__device__ int2  g_edge[1600000];
__device__ unsigned g_barc;   // monotonic arrival counter
__device__ unsigned g_bars;   // release phase flag

// Device-wide barrier (all nb blocks co-resident). Monotonic phases 1,2,3,...
__device__ __forceinline__ void gsync(unsigned phase, int nb) {
    __syncthreads();
    if (threadIdx.x == 0) {
        __threadfence();
        atomicAdd(&g_barc, 1u);
        if (blockIdx.x == 0) {
            while (atomicAdd(&g_barc, 0u) < (unsigned)nb * phase) __nanosleep(64);
            atomicExch(&g_bars, phase);
        } else {
            while (atomicAdd(&g_bars, 0u) < phase) __nanosleep(64);
        }
        __threadfence();
    }
    __syncthreads();
}

// ---------------------------------------------------------------------------
// Per-node aggregation (warp-collective; lane owns float4 of 128 features).
// Returns acc = dinv[w]^2*in[w] + sum_e norm[e]*in[src[e]]. MLP=8 inner loop.
// ---------------------------------------------------------------------------
__device__ __forceinline__ float4 aggr_node(const float* __restrict__ in,
                                            int w, int lane) {
    const int beg = g_ptr[w];
    const int end = beg + g_cnt[w];
    const float dv = g_dinv[w];
    const float s = dv * dv;

    float4 acc = *(const float4*)&in[(size_t)w * 128 + lane * 4];
    acc.x *= s; acc.y *= s; acc.z *= s; acc.w *= s;

    for (int base = beg; base < end; base += 32) {
        const int idx = base + lane;
        const int2 ed = (idx < end) ? g_edge[idx] : make_int2(0, 0);
        const int m = min(32, end - base);
        int j = 0;
        for (; j + 8 <= m; j += 8) {
            int sx[8];
            float nm[8];
#pragma unroll
            for (int q = 0; q < 8; q++) {
                sx[q] = __shfl_sync(0xffffffffu, ed.x, j + q);
                nm[q] = __int_as_float(__shfl_sync(0xffffffffu, ed.y, j + q));
            }
            float4 v[8];
#pragma unroll
            for (int q = 0; q < 8; q++)
                v[q] = *(const float4*)&in[(size_t)sx[q] * 128 + lane * 4];
#pragma unroll
            for (int q = 0; q < 8; q++) {
                acc.x = fmaf(nm[q], v[q].x, acc.x);
                acc.y = fmaf(nm[q], v[q].y, acc.y);
                acc.z = fmaf(nm[q], v[q].z, acc.z);
                acc.w = fmaf(nm[q], v[q].w, acc.w);
            }
        }
        for (; j + 4 <= m; j += 4) {
            const int s0 = __shfl_sync(0xffffffffu, ed.x, j + 0);
            const int s1 = __shfl_sync(0xffffffffu, ed.x, j + 1);
            const int s2 = __shfl_sync(0xffffffffu, ed.x, j + 2);
            const int s3 = __shfl_sync(0xffffffffu, ed.x, j + 3);
            const float n0 = __int_as_float(__shfl_sync(0xffffffffu, ed.y, j + 0));
            const float n1 = __int_as_float(__shfl_sync(0xffffffffu, ed.y, j + 1));
            const float n2 = __int_as_float(__shfl_sync(0xffffffffu, ed.y, j + 2));
            const float n3 = __int_as_float(__shfl_sync(0xffffffffu, ed.y, j + 3));
            const float4 v0 = *(const float4*)&in[(size_t)s0 * 128 + lane * 4];
            const float4 v1 = *(const float4*)&in[(size_t)s1 * 128 + lane * 4];
            const float4 v2 = *(const float4*)&in[(size_t)s2 * 128 + lane * 4];
            const float4 v3 = *(const float4*)&in[(size_t)s3 * 128 + lane * 4];
            acc.x = fmaf(n0, v0.x, acc.x); acc.y = fmaf(n0, v0.y, acc.y);
            acc.z = fmaf(n0, v0.z, acc.z); acc.w = fmaf(n0, v0.w, acc.w);
            acc.x = fmaf(n1, v1.x, acc.x); acc.y = fmaf(n1, v1.y, acc.y);
            acc.z = fmaf(n1, v1.z, acc.z); acc.w = fmaf(n1, v1.w, acc.w);
            acc.x = fmaf(n2, v2.x, acc.x); acc.y = fmaf(n2, v2.y, acc.y);
            acc.z = fmaf(n2, v2.z, acc.z); acc.w = fmaf(n2, v2.w, acc.w);
            acc.x = fmaf(n3, v3.x, acc.x); acc.y = fmaf(n3, v3.y, acc.y);
            acc.z = fmaf(n3, v3.z, acc.z); acc.w = fmaf(n3, v3.w, acc.w);
        }
        for (; j < m; j++) {
            const int s0 = __shfl_sync(0xffffffffu, ed.x, j);
            const float n0 = __int_as_float(__shfl_sync(0xffffffffu, ed.y, j));
            const float4 v0 = *(const float4*)&in[(size_t)s0 * 128 + lane * 4];
            acc.x = fmaf(n0, v0.x, acc.x); acc.y = fmaf(n0, v0.y, acc.y);
            acc.z = fmaf(n0, v0.z, acc.z); acc.w = fmaf(n0, v0.w, acc.w);
        }
    }
    return acc;
}

// ---------------------------------------------------------------------------
// Fused layer: per tile of M nodes, aggregate directly into the WMMA A-tile
// (bf16 hi/lo in smem), then tensor-core GEMM + bias (+ReLU) to B.
// B[v,:] = relu( (Â·in)[v,:] @ W + bias )
// 12 warps; each warp: M/12 nodes aggregated; 1 m-tile x 2 n-tiles in MMA.
// ---------------------------------------------------------------------------
template <int DO, int M, bool RELU>
__device__ void layer_fused(const float* __restrict__ in, const float* __restrict__ W,
                            const float* __restrict__ bias, float* __restrict__ B,
                            int N, char* smem, int nb) {
    constexpr int LDW = DO + 8;        // padded W row
    constexpr int LDA = 136;           // padded A row (128 + 8)
    constexpr int NT = DO / 16;        // n-tiles
    constexpr int TPW = 2;             // n-tiles per warp
    constexpr int WPR = NT / TPW;      // warps per m-tile row
    static_assert((M / 16) * WPR == WARPS, "all warps used");
    __nv_bfloat16* w_hi = (__nv_bfloat16*)smem;
    __nv_bfloat16* w_lo = w_hi + 128 * LDW;
    __nv_bfloat16* a_hi = w_lo + 128 * LDW;
    __nv_bfloat16* a_lo = a_hi + M * LDA;
    float* outs = (float*)(w_lo + 128 * LDW);  // aliases a_hi/a_lo after MMA

    const int tid = threadIdx.x;
    const int warp = tid >> 5;
    const int lane = tid & 31;
    const int wm = warp / WPR;           // m-tile
    const int wn0 = (warp % WPR) * TPW;  // first n-tile

    // stage W -> bf16 hi/lo (once per phase)
    for (int i = tid; i < 128 * DO / 4; i += TPB) {
        const int r = i / (DO / 4);
        const int c4 = i % (DO / 4);
        const float4 v = *(const float4*)&W[r * DO + c4 * 4];
        __nv_bfloat16 h0 = __float2bfloat16(v.x), h1 = __float2bfloat16(v.y);
        __nv_bfloat16 h2 = __float2bfloat16(v.z), h3 = __float2bfloat16(v.w);
        __nv_bfloat16* ph = &w_hi[r * LDW + c4 * 4];
        __nv_bfloat16* pl = &w_lo[r * LDW + c4 * 4];
        ph[0] = h0; ph[1] = h1; ph[2] = h2; ph[3] = h3;
        pl[0] = __float2bfloat16(v.x - __bfloat162float(h0));
        pl[1] = __float2bfloat16(v.y - __bfloat162float(h1));
        pl[2] = __float2bfloat16(v.z - __bfloat162float(h2));
        pl[3] = __float2bfloat16(v.w - __bfloat162float(h3));
    }

    const int n_tiles = (N + M - 1) / M;
    for (int tile = blockIdx.x; tile < n_tiles; tile += nb) {
        const int base = tile * M;
        __syncthreads();  // W staged / outs (a-region) free from previous tile

        // aggregate this tile's nodes straight into the A-tile (bf16 hi/lo)
        for (int i = warp; i < M; i += WARPS) {
            const int node = base + i;
            float4 acc = make_float4(0.f, 0.f, 0.f, 0.f);
            if (node < N) acc = aggr_node(in, node, lane);
            __nv_bfloat16 h0 = __float2bfloat16(acc.x), h1 = __float2bfloat16(acc.y);
            __nv_bfloat16 h2 = __float2bfloat16(acc.z), h3 = __float2bfloat16(acc.w);
            __nv_bfloat162 hp0; hp0.x = h0; hp0.y = h1;
            __nv_bfloat162 hp1; hp1.x = h2; hp1.y = h3;
            __nv_bfloat162 lp0, lp1;
            lp0.x = __float2bfloat16(acc.x - __bfloat162float(h0));
            lp0.y = __float2bfloat16(acc.y - __bfloat162float(h1));
            lp1.x = __float2bfloat16(acc.z - __bfloat162float(h2));
            lp1.y = __float2bfloat16(acc.w - __bfloat162float(h3));
            *(__nv_bfloat162*)&a_hi[i * LDA + lane * 4]     = hp0;
            *(__nv_bfloat162*)&a_hi[i * LDA + lane * 4 + 2] = hp1;
            *(__nv_bfloat162*)&a_lo[i * LDA + lane * 4]     = lp0;
            *(__nv_bfloat162*)&a_lo[i * LDA + lane * 4 + 2] = lp1;
        }
        __syncthreads();

        wmma::fragment<wmma::accumulator, 16, 16, 16, float> acc[TPW];
#pragma unroll
        for (int t = 0; t < TPW; t++) wmma::fill_fragment(acc[t], 0.0f);

#pragma unroll
        for (int k = 0; k < 128; k += 16) {
            wmma::fragment<wmma::matrix_a, 16, 16, 16, __nv_bfloat16, wmma::row_major> fah, fal;
            wmma::load_matrix_sync(fah, a_hi + wm * 16 * LDA + k, LDA);
            wmma::load_matrix_sync(fal, a_lo + wm * 16 * LDA + k, LDA);
#pragma unroll
            for (int t = 0; t < TPW; t++) {
                const int nt = wn0 + t;
                wmma::fragment<wmma::matrix_b, 16, 16, 16, __nv_bfloat16, wmma::row_major> fbh, fbl;
                wmma::load_matrix_sync(fbh, w_hi + k * LDW + nt * 16, LDW);
                wmma::load_matrix_sync(fbl, w_lo + k * LDW + nt * 16, LDW);
                wmma::mma_sync(acc[t], fah, fbh, acc[t]);
                wmma::mma_sync(acc[t], fah, fbl, acc[t]);
                wmma::mma_sync(acc[t], fal, fbh, acc[t]);
            }
        }

        __syncthreads();  // all warps done reading a_hi/a_lo (outs aliases them)
#pragma unroll
        for (int t = 0; t < TPW; t++)
            wmma::store_matrix_sync(outs + wm * 16 * DO + (wn0 + t) * 16, acc[t],
                                    DO, wmma::mem_row_major);
        __syncthreads();

        // epilogue: bias + optional relu, write to global
        for (int i = tid; i < M * DO / 4; i += TPB) {
            const int r = i / (DO / 4);
            const int c4 = i % (DO / 4);
            const int node = base + r;
            if (node < N) {
                float4 v = *(const float4*)&outs[r * DO + c4 * 4];
                const float4 bb = *(const float4*)&bias[c4 * 4];
                v.x += bb.x; v.y += bb.y; v.z += bb.z; v.w += bb.w;
                if (RELU) {
                    v.x = fmaxf(v.x, 0.f); v.y = fmaxf(v.y, 0.f);
                    v.z = fmaxf(v.z, 0.f); v.w = fmaxf(v.w, 0.f);
                }
                *(float4*)&B[(size_t)node * DO + c4 * 4] = v;
            }
        }
    }
}

// ---------------------------------------------------------------------------
// The fused persistent kernel: whole 3-layer GCN in one launch.
// Per layer: ONE fused aggr+GEMM phase (no g_h intermediate), one gsync.
// ---------------------------------------------------------------------------
__global__ void __launch_bounds__(TPB, 2)
k_fused(const float* __restrict__ x,
        const int* __restrict__ row, const int* __restrict__ col,
        const float* __restrict__ W1, const float* __restrict__ b1,
        const float* __restrict__ W2, const float* __restrict__ b2,
        const float* __restrict__ W3, const float* __restrict__ b3,
        float* __restrict__ out, int N, int E, int nb) {
    extern __shared__ char sh[];
    const int gtid = blockIdx.x * TPB + threadIdx.x;
    const int gthreads = nb * TPB;
    const int gwarp = gtid >> 5;
    const int nwarps = gthreads >> 5;
    const int lane = threadIdx.x & 31;

    // P0: degree histogram (g_cnt zero by invariant)
    for (int e = gtid; e < E; e += gthreads) atomicAdd(&g_cnt[col[e]], 1);
    gsync(1, nb);

    // P1: segment alloc (warp scan + global cursor) + dinv
    for (int cb = gwarp; cb * 32 < N; cb += nwarps) {
        const int i = cb * 32 + lane;
        const int c = (i < N) ? g_cnt[i] : 0;
        int p = c;
#pragma unroll
        for (int off = 1; off < 32; off <<= 1) {
            const int t = __shfl_up_sync(0xffffffffu, p, off);
            if (lane >= off) p += t;
        }
        const int total = __shfl_sync(0xffffffffu, p, 31);
        int base = 0;
        if (lane == 31) base = atomicAdd(&g_cursor, total);
        base = __shfl_sync(0xffffffffu, base, 31);
        if (i < N) {
            g_ptr[i] = base + p - c;
            g_dinv[i] = rsqrtf((float)(c + 1));  // +1 self-loop
        }
    }
    gsync(2, nb);

    // P2: fill edges {src, norm}
    for (int e = gtid; e < E; e += gthreads) {
        const int c = col[e];
        const int r = row[e];
        const int pos = g_ptr[c] + atomicAdd(&g_fill[c], 1);
        g_edge[pos] = make_int2(r, __float_as_int(g_dinv[r] * g_dinv[c]));
    }
    gsync(3, nb);

    // layer 1: fused aggr(x) + GEMM1 -> g_xw
    layer_fused<128, 48, true>(x, W1, b1, g_xw, N, sh, nb);
    gsync(4, nb);

    // layer 2: fused aggr(g_xw) + GEMM2 -> g_xw (in-place hazard? no:
    // aggregation for a tile reads arbitrary rows of the PREVIOUS layer's
    // g_xw, but GEMM2 writes the same array. Use the second half-buffer.)
    layer_fused<128, 48, true>(g_xw, W2, b2, (float*)g_edge == nullptr ? g_xw : g_xw, N, sh, nb);
    gsync(5, nb);

    // layer 3: fused aggr + GEMM3 -> out
    layer_fused<64, 96, false>(g_xw, W3, b3, out, N, sh, nb);
    gsync(6, nb);

    // cleanup (restore zero-invariant) — after fused3 finished reading g_cnt
    for (int i = gtid; i < N; i += gthreads) { g_cnt[i] = 0; g_fill[i] = 0; }
    if (gtid == 0) g_cursor = 0;

    // epilogue: reset barrier state after all blocks passed gsync(6)+cleanup.
    __syncthreads();
    if (threadIdx.x == 0) {
        __threadfence();
        if (blockIdx.x != 0) {
            atomicAdd(&g_barc, 1u);
        } else {
            while (atomicAdd(&g_barc, 0u) < (unsigned)nb * 6u + (unsigned)(nb - 1))
                __nanosleep(64);
            atomicExch(&g_barc, 0u);
            atomicExch(&g_bars, 0u);
        }
    }
}

// Layer-2 in-place hazard fix: aggregation of layer 2 reads g_xw rows written
// by layer-1 GEMM, while layer-2 GEMM writes g_xw rows of its own tile. A
// block's tile write happens only AFTER it aggregated that tile, but OTHER
// blocks may still be aggregating nodes whose neighbors are in this tile.
// => need double buffer. g_h serves as the layer-2 output buffer.
__device__ float g_h2[100000 * 128];

__global__ void __launch_bounds__(TPB, 2)
k_fused2(const float* __restrict__ x,
         const int* __restrict__ row, const int* __restrict__ col,
         const float* __restrict__ W1, const float* __restrict__ b1,
         const float* __restrict__ W2, const float* __restrict__ b2,
         const float* __restrict__ W3, const float* __restrict__ b3,
         float* __restrict__ out, int N, int E, int nb) {
    extern __shared__ char sh[];
    const int gtid = blockIdx.x * TPB + threadIdx.x;
    const int gthreads = nb * TPB;
    const int gwarp = gtid >> 5;
    const int nwarps = gthreads >> 5;
    const int lane = threadIdx.x & 31;

    for (int e = gtid; e < E; e += gthreads) atomicAdd(&g_cnt[col[e]], 1);
    gsync(1, nb);

    for (int cb = gwarp; cb * 32 < N; cb += nwarps) {
        const int i = cb * 32 + lane;
        const int c = (i < N) ? g_cnt[i] : 0;
        int p = c;
#pragma unroll
        for (int off = 1; off < 32; off <<= 1) {
            const int t = __shfl_up_sync(0xffffffffu, p, off);
            if (lane >= off) p += t;
        }
        const int total = __shfl_sync(0xffffffffu, p, 31);
        int base = 0;
        if (lane == 31) base = atomicAdd(&g_cursor, total);
        base = __shfl_sync(0xffffffffu, base, 31);
        if (i < N) {
            g_ptr[i] = base + p - c;
            g_dinv[i] = rsqrtf((float)(c + 1));
        }
    }
    gsync(2, nb);

    for (int e = gtid; e < E; e += gthreads) {
        const int c = col[e];
        const int r = row[e];
        const int pos = g_ptr[c] + atomicAdd(&g_fill[c], 1);
        g_edge[pos] = make_int2(r, __float_as_int(g_dinv[r] * g_dinv[c]));
    }
    gsync(3, nb);

    layer_fused<128, 48, true>(x, W1, b1, g_xw, N, sh, nb);    // -> g_xw
    gsync(4, nb);
    layer_fused<128, 48, true>(g_xw, W2, b2, g_h2, N, sh, nb); // -> g_h2
    gsync(5, nb);
    layer_fused<64, 96, false>(g_h2, W3, b3, out, N, sh, nb);  // -> out
    gsync(6, nb);

    for (int i = gtid; i < N; i += gthreads) { g_cnt[i] = 0; g_fill[i] = 0; }
    if (gtid == 0) g_cursor = 0;

    __syncthreads();
    if (threadIdx.x == 0) {
        __threadfence();
        if (blockIdx.x != 0) {
            atomicAdd(&g_barc, 1u);
        } else {
            while (atomicAdd(&g_barc, 0u) < (unsigned)nb * 6u + (unsigned)(nb - 1))
                __nanosleep(64);
            atomicExch(&g_barc, 0u);
            atomicExch(&g_bars, 0u);
        }
    }
}

// ---------------------------------------------------------------------------
// launch — ONE kernel (k_fused2: double-buffered, hazard-free)
// ---------------------------------------------------------------------------
extern "C" void kernel_launch(void* const* d_in, const int* in_sizes, int n_in,
                              void* d_out, int out_size) {
    const float* x  = (const float*)d_in[0];
    const int*   ei = (const int*)d_in[1];
    const float* W1 = (const float*)d_in[2];
    const float* b1 = (const float*)d_in[3];
    const float* W2 = (const float*)d_in[4];
    const float* b2 = (const float*)d_in[5];
    const float* W3 = (const float*)d_in[6];
    const float* b3 = (const float*)d_in[7];
    float* out = (float*)d_out;

    const int N = in_sizes[0] / 128;
    const int E = in_sizes[1] / 2;
    const int* row = ei;
    const int* col = ei + E;

    cudaFuncSetAttribute(k_fused2, cudaFuncAttributeMaxDynamicSharedMemorySize, SMEM_BYTES);

    int dev = 0;
    cudaGetDevice(&dev);
    int sms = 0;
    cudaDeviceGetAttribute(&sms, cudaDevAttrMultiProcessorCount, dev);
    int bpm = 0;
    cudaOccupancyMaxActiveBlocksPerMultiprocessor(&bpm, k_fused2, TPB, SMEM_BYTES);
    if (bpm < 1) bpm = 1;
    if (bpm > 2) bpm = 2;
    const int nb = sms * bpm;   // all blocks co-resident -> gsync is safe

    k_fused2<<<nb, TPB, SMEM_BYTES>>>(x, row, col, W1, b1, W2, b2, W3, b3, out, N, E, nb);
}